// round 15
// baseline (speedup 1.0000x reference)
#include <cuda_runtime.h>
#include <cuda_bf16.h>
#include <stdint.h>

#define BB 64
#define HH 512
#define WW 512
#define CC 3
#define ROWF (WW * CC)     // 1536 floats per row
#define ROWV (ROWF / 4)    // 384 float4 per row
#define RPB 4              // rows per block

__global__ __launch_bounds__(ROWV) void cutmix_kernel(
    const float* __restrict__ x,
    const int*   __restrict__ y1,
    const int*   __restrict__ y2,
    const int*   __restrict__ x1,
    const int*   __restrict__ x2,
    const int*   __restrict__ perm,
    float*       __restrict__ out)
{
    // h-major ordering: consecutive blocks -> same row group, different image.
    // One wave covers a row band of ALL images, so donor-box reads hit L2
    // lines fetched by the donor image's own block in the same wave.
    const int b  = blockIdx.x & (BB - 1);
    const int h0 = (blockIdx.x >> 6) * RPB;

    // Per-block scalar metadata (L2-resident, uniform across block)
    const int ya = __ldg(&y1[b]);
    const int yb = __ldg(&y2[b]);
    const int xa = __ldg(&x1[b]);
    const int xb = __ldg(&x2[b]);
    const int pb = __ldg(&perm[b]);

    const int t  = threadIdx.x;          // 0 .. 383
    const int j  = t * 4;                // first float index in row
    const int w0 = j / 3;                // pixel of first element
    const int w1 = (j + 3) / 3;          // pixel of last element

    const bool p0 = (w0 >= xa) & (w0 < xb);
    const bool p1 = (w1 >= xa) & (w1 < xb);

    const float4* __restrict__ xv = reinterpret_cast<const float4*>(x);
    float4* __restrict__ ov = reinterpret_cast<float4*>(out);

    float4 v[RPB];

    if (p0 == p1) {
        // Uniform chunk: one vector load per row, source row selected by
        // address. All RPB loads issued before any store (front-batched MLP).
        #pragma unroll
        for (int r = 0; r < RPB; r++) {
            const int h = h0 + r;
            const bool hin = (h >= ya) & (h < yb);
            const int sb = (hin & p0) ? pb : b;
            v[r] = __ldg(&xv[((size_t)sb * HH + h) * ROWV + t]);
        }
    } else {
        // Chunk straddles x1/x2 boundary (2 of 384 threads per row): blend.
        #pragma unroll
        for (int r = 0; r < RPB; r++) {
            const int h = h0 + r;
            const bool hin = (h >= ya) & (h < yb);
            float4 a = xv[((size_t)b * HH + h) * ROWV + t];
            if (hin) {
                float4 s = xv[((size_t)pb * HH + h) * ROWV + t];
                const float* af = reinterpret_cast<const float*>(&a);
                const float* sf = reinterpret_cast<const float*>(&s);
                float rr[4];
                #pragma unroll
                for (int k = 0; k < 4; k++) {
                    const int w = (j + k) / 3;
                    const bool p = (w >= xa) & (w < xb);
                    rr[k] = p ? sf[k] : af[k];
                }
                a = make_float4(rr[0], rr[1], rr[2], rr[3]);
            }
            v[r] = a;
        }
    }

    // Write-through stores: do not allocate L2 lines for the output stream;
    // output is never re-read, so L2 stays a read cache for x (intra-wave
    // donor hits + cross-replay residency).
    #pragma unroll
    for (int r = 0; r < RPB; r++) {
        const int h = h0 + r;
        __stwt(&ov[((size_t)b * HH + h) * ROWV + t], v[r]);
    }
}

extern "C" void kernel_launch(void* const* d_in, const int* in_sizes, int n_in,
                              void* d_out, int out_size)
{
    const float* x    = (const float*)d_in[0];
    const int*   y1   = (const int*)  d_in[1];
    const int*   y2   = (const int*)  d_in[2];
    const int*   x1   = (const int*)  d_in[3];
    const int*   x2   = (const int*)  d_in[4];
    const int*   perm = (const int*)  d_in[5];
    float*       out  = (float*)      d_out;

    (void)in_sizes; (void)n_in; (void)out_size;

    cutmix_kernel<<<(BB * HH) / RPB, ROWV>>>(x, y1, y2, x1, x2, perm, out);
}

// round 16
// speedup vs baseline: 1.0170x; 1.0170x over previous
#include <cuda_runtime.h>
#include <cuda_bf16.h>
#include <stdint.h>

#define BB 64
#define HH 512
#define WW 512
#define CC 3
#define ROWF (WW * CC)     // 1536 floats per row
#define ROWV (ROWF / 4)    // 384 float4 per row
#define RPB 4              // rows per block

__global__ __launch_bounds__(ROWV) void cutmix_kernel(
    const float* __restrict__ x,
    const int*   __restrict__ y1,
    const int*   __restrict__ y2,
    const int*   __restrict__ x1,
    const int*   __restrict__ x2,
    const int*   __restrict__ perm,
    float*       __restrict__ out)
{
    // h-major ordering: consecutive blocks -> same row group, different image.
    // One wave covers a row band of ALL images, so donor-box reads hit L2
    // lines fetched by the donor image's own block in the same wave.
    const int b  = blockIdx.x & (BB - 1);
    const int h0 = (blockIdx.x >> 6) * RPB;

    // Per-block scalar metadata (L2-resident, uniform across block)
    const int ya = __ldg(&y1[b]);
    const int yb = __ldg(&y2[b]);
    const int xa = __ldg(&x1[b]);
    const int xb = __ldg(&x2[b]);
    const int pb = __ldg(&perm[b]);

    const int t  = threadIdx.x;          // 0 .. 383
    const int j  = t * 4;                // first float index in row
    const int w0 = j / 3;                // pixel of first element
    const int w1 = (j + 3) / 3;          // pixel of last element

    const bool p0 = (w0 >= xa) & (w0 < xb);
    const bool p1 = (w1 >= xa) & (w1 < xb);

    const float4* __restrict__ xv = reinterpret_cast<const float4*>(x);
    float4* __restrict__ ov = reinterpret_cast<float4*>(out);

    float4 v[RPB];

    if (p0 == p1) {
        // Uniform chunk: one vector load per row, source row selected by
        // address. All RPB loads issued before any store (front-batched MLP).
        #pragma unroll
        for (int r = 0; r < RPB; r++) {
            const int h = h0 + r;
            const bool hin = (h >= ya) & (h < yb);
            const int sb = (hin & p0) ? pb : b;
            v[r] = __ldg(&xv[((size_t)sb * HH + h) * ROWV + t]);
        }
    } else {
        // Chunk straddles x1/x2 boundary (2 of 384 threads per row): blend.
        #pragma unroll
        for (int r = 0; r < RPB; r++) {
            const int h = h0 + r;
            const bool hin = (h >= ya) & (h < yb);
            float4 a = xv[((size_t)b * HH + h) * ROWV + t];
            if (hin) {
                float4 s = xv[((size_t)pb * HH + h) * ROWV + t];
                const float* af = reinterpret_cast<const float*>(&a);
                const float* sf = reinterpret_cast<const float*>(&s);
                float rr[4];
                #pragma unroll
                for (int k = 0; k < 4; k++) {
                    const int w = (j + k) / 3;
                    const bool p = (w >= xa) & (w < xb);
                    rr[k] = p ? sf[k] : af[k];
                }
                a = make_float4(rr[0], rr[1], rr[2], rr[3]);
            }
            v[r] = a;
        }
    }

    // Write-through stores: do not allocate L2 lines for the output stream;
    // output is never re-read, so L2 stays a read cache for x (intra-wave
    // donor hits + cross-replay residency).
    #pragma unroll
    for (int r = 0; r < RPB; r++) {
        const int h = h0 + r;
        __stwt(&ov[((size_t)b * HH + h) * ROWV + t], v[r]);
    }
}

extern "C" void kernel_launch(void* const* d_in, const int* in_sizes, int n_in,
                              void* d_out, int out_size)
{
    const float* x    = (const float*)d_in[0];
    const int*   y1   = (const int*)  d_in[1];
    const int*   y2   = (const int*)  d_in[2];
    const int*   x1   = (const int*)  d_in[3];
    const int*   x2   = (const int*)  d_in[4];
    const int*   perm = (const int*)  d_in[5];
    float*       out  = (float*)      d_out;

    (void)in_sizes; (void)n_in; (void)out_size;

    cutmix_kernel<<<(BB * HH) / RPB, ROWV>>>(x, y1, y2, x1, x2, perm, out);
}